// round 12
// baseline (speedup 1.0000x reference)
#include <cuda_runtime.h>
#include <math.h>

#define K 32
#define G 256
#define XMIN -6.5f
#define RANGE 13.0f
#define INV_H (G / RANGE)
#define H_STEP (RANGE / G)
#define INV_SQRT_2PI 0.3989422804014327f
#define S_CONST 0.8493218002880191f  // sqrt(0.5*log2(e))
#define EPS 2.2204460492503131e-16f
#define NCHUNK 9                     // ceil((G-1)/31)
#define WPB 8                        // warps per block (256 threads)

__device__ float2 g_tabF[G * K];  // (value, delta) per (g, comp)
__device__ float2 g_tabI[G * K];

__device__ __forceinline__ float ex2f(float x) {
    float r;
    asm("ex2.approx.ftz.f32 %0, %1;" : "=f"(r) : "f"(x));
    return r;
}

// ---------------- fused prep + build (float2: value + delta) ----------------
__global__ void __launch_bounds__(512) build_kernel(const float* __restrict__ Wk0,
                                                    const float* __restrict__ W10,
                                                    const float* __restrict__ W21,
                                                    const float* __restrict__ mu,
                                                    const float* __restrict__ sigma) {
    __shared__ float4 s_tab[K * K];
    __shared__ float w0s[K];

    int lane = threadIdx.x & 31;
    int w = threadIdx.x >> 5;

    if (w == 0) {
        float v = Wk0[lane];
        float mx = v;
#pragma unroll
        for (int o = 16; o; o >>= 1) mx = fmaxf(mx, __shfl_xor_sync(~0u, mx, o));
        float e = __expf(v - mx);
        float s = e;
#pragma unroll
        for (int o = 16; o; o >>= 1) s += __shfl_xor_sync(~0u, s, o);
        w0s[lane] = e / s;
    }

    float w10v[2], w21v[2], sgv[2], muv[2];
#pragma unroll
    for (int c = 0; c < 2; c++) {
        int j = w + c * 16;
        int idx = lane * K + j;
        float v10 = W10[idx];
        float v21 = W21[idx];
        sgv[c] = sigma[idx];
        muv[c] = mu[idx];
        float mx10 = v10, mx21 = v21;
#pragma unroll
        for (int o = 16; o; o >>= 1) {
            mx10 = fmaxf(mx10, __shfl_xor_sync(~0u, mx10, o));
            mx21 = fmaxf(mx21, __shfl_xor_sync(~0u, mx21, o));
        }
        float e10 = __expf(v10 - mx10);
        float e21 = __expf(v21 - mx21);
        float s10 = e10, s21 = e21;
#pragma unroll
        for (int o = 16; o; o >>= 1) {
            s10 += __shfl_xor_sync(~0u, s10, o);
            s21 += __shfl_xor_sync(~0u, s21, o);
        }
        w10v[c] = e10 / s10;
        w21v[c] = e21 / s21;
    }
    __syncthreads();

#pragma unroll
    for (int c = 0; c < 2; c++) {
        int j = w + c * 16;
        float inv_sg = 1.f / sgv[c];
        float4 t;
        t.x = S_CONST * inv_sg;
        t.y = -S_CONST * muv[c] * inv_sg;
        t.z = w21v[c] * INV_SQRT_2PI * inv_sg;
        t.w = w10v[c] * w0s[j] * INV_SQRT_2PI * inv_sg;
        s_tab[lane * K + j] = t;
    }
    __syncthreads();

    int chunk = blockIdx.x;
    int tsel = blockIdx.y;
    int g = chunk * 31 + lane;
    if (g > G - 1) g = G - 1;
    float x = XMIN + g * H_STEP;

#pragma unroll
    for (int c = 0; c < 2; c++) {
        int f = w + c * 16;
        float v = 0.f;
        if (tsel == 0) {
#pragma unroll
            for (int j = 0; j < K; j++) {
                float4 t = s_tab[f * K + j];
                float u = fmaf(x, t.x, t.y);
                v = fmaf(t.w, ex2f(-u * u), v);
            }
        } else {
#pragma unroll
            for (int i = 0; i < K; i++) {
                float4 t = s_tab[i * K + f];
                float u = fmaf(x, t.x, t.y);
                v = fmaf(t.z, ex2f(-u * u), v);
            }
        }
        float vn = __shfl_down_sync(0xffffffffu, v, 1);
        if (lane < 31 && g < G - 1) {
            float2 e;
            e.x = v;
            e.y = vn - v;
            if (tsel == 0) g_tabF[g * K + f] = e;
            else           g_tabI[g * K + f] = e;
        }
    }
}

// ---------------- main: 16 samples/warp, L1-resident tables, 64-reg cap ----------------
__global__ void __launch_bounds__(256, 4) tt_main(const float* __restrict__ X,
                                                  float* __restrict__ out,
                                                  int n, int ntasks) {
    __shared__ float4 sp[WPB][16];
    __shared__ float prodm[WPB][16][17];

    int tid = threadIdx.x;
    int lane = tid & 31;
    int w = tid >> 5;

    int task = blockIdx.x * WPB + w;
    if (task >= ntasks) return;

    int base = task * 16;

    if (lane < 16) {
        int sidx = base + lane;
        float2 x = make_float2(0.f, 0.f);
        if (sidx < n) x = ((const float2*)X)[sidx];
        float t0 = (x.x - XMIN) * INV_H;
        float t1 = (x.y - XMIN) * INV_H;
        float g0f = fminf(fmaxf(floorf(t0), 0.f), (float)(G - 2));
        float g1f = fminf(fmaxf(floorf(t1), 0.f), (float)(G - 2));
        sp[w][lane] = make_float4(g0f, t0 - g0f, g1f, t1 - g1f);
    }
    __syncwarp();

    const float4* tF = (const float4*)g_tabF;  // row g: 16 float4 (comps 2p,2p+1 as v,d)
    const float4* tI = (const float4*)g_tabI;

    int half = lane >> 4;   // lanes 0-15: even sample of pair; 16-31: odd
    int pair = lane & 15;   // component pair (comps 2p, 2p+1)

#pragma unroll
    for (int t = 0; t < 8; t++) {
        float4 p = sp[w][2 * t + half];
        float4 fF = __ldg(&tF[((int)p.x) * 16 + pair]);
        float4 fI = __ldg(&tI[((int)p.z) * 16 + pair]);
        float vF0 = fmaf(p.y, fF.y, fF.x);
        float vF1 = fmaf(p.y, fF.w, fF.z);
        float vI0 = fmaf(p.w, fI.y, fI.x);
        float vI1 = fmaf(p.w, fI.w, fI.z);
        prodm[w][2 * t + half][pair] = vF0 * vI0 + vF1 * vI1;
    }
    __syncwarp();

    // split reduction: two lanes per sample, 8 terms each, then one shfl
    int s = lane & 15;
    int off = half * 8;
    float acc = 0.f;
#pragma unroll
    for (int i = 0; i < 8; i++) acc += prodm[w][s][off + i];
    acc += __shfl_xor_sync(~0u, acc, 16);

    if (lane < 16) {
        int sidx = base + lane;
        if (sidx < n) out[sidx] = __logf(acc + EPS);
    }
}

extern "C" void kernel_launch(void* const* d_in, const int* in_sizes, int n_in,
                              void* d_out, int out_size) {
    const float* X     = (const float*)d_in[0];
    const float* Wk0   = (const float*)d_in[1];
    const float* Wk1k0 = (const float*)d_in[2];
    const float* Wk2k1 = (const float*)d_in[3];
    const float* mu    = (const float*)d_in[4];
    const float* sigma = (const float*)d_in[5];
    float* out = (float*)d_out;
    int n = in_sizes[0] / 2;

    build_kernel<<<dim3(NCHUNK, 2), 512>>>(Wk0, Wk1k0, Wk2k1, mu, sigma);
    int ntasks = (n + 15) / 16;
    int blocks = (ntasks + WPB - 1) / WPB;
    tt_main<<<blocks, 256>>>(X, out, n, ntasks);
}

// round 13
// speedup vs baseline: 1.1987x; 1.1987x over previous
#include <cuda_runtime.h>
#include <cuda_fp16.h>
#include <math.h>

#define K 32
#define G 256
#define XMIN -6.5f
#define RANGE 13.0f
#define INV_H (G / RANGE)
#define H_STEP (RANGE / G)
#define INV_SQRT_2PI 0.3989422804014327f
#define S_CONST 0.8493218002880191f  // sqrt(0.5*log2(e))
#define EPS 2.2204460492503131e-16f
#define NCHUNK 9                     // ceil((G-1)/31)
#define WPB 8                        // warps per block (256 threads)

// fp16 tables: row g = 128B = 8 x uint4; group q holds comps 4q..4q+3 as
// [v0 v1 v2 v3 d0 d1 d2 d3] (halves)
__device__ __half g_tabF16[G * K * 2];
__device__ __half g_tabI16[G * K * 2];

__device__ __forceinline__ float ex2f(float x) {
    float r;
    asm("ex2.approx.ftz.f32 %0, %1;" : "=f"(r) : "f"(x));
    return r;
}

// ---------------- fused prep + build ----------------
__global__ void __launch_bounds__(512) build_kernel(const float* __restrict__ Wk0,
                                                    const float* __restrict__ W10,
                                                    const float* __restrict__ W21,
                                                    const float* __restrict__ mu,
                                                    const float* __restrict__ sigma) {
    __shared__ float4 s_tab[K * K];
    __shared__ float w0s[K];

    int lane = threadIdx.x & 31;
    int w = threadIdx.x >> 5;

    if (w == 0) {
        float v = Wk0[lane];
        float mx = v;
#pragma unroll
        for (int o = 16; o; o >>= 1) mx = fmaxf(mx, __shfl_xor_sync(~0u, mx, o));
        float e = __expf(v - mx);
        float s = e;
#pragma unroll
        for (int o = 16; o; o >>= 1) s += __shfl_xor_sync(~0u, s, o);
        w0s[lane] = e / s;
    }

    float w10v[2], w21v[2], sgv[2], muv[2];
#pragma unroll
    for (int c = 0; c < 2; c++) {
        int j = w + c * 16;
        int idx = lane * K + j;
        float v10 = W10[idx];
        float v21 = W21[idx];
        sgv[c] = sigma[idx];
        muv[c] = mu[idx];
        float mx10 = v10, mx21 = v21;
#pragma unroll
        for (int o = 16; o; o >>= 1) {
            mx10 = fmaxf(mx10, __shfl_xor_sync(~0u, mx10, o));
            mx21 = fmaxf(mx21, __shfl_xor_sync(~0u, mx21, o));
        }
        float e10 = __expf(v10 - mx10);
        float e21 = __expf(v21 - mx21);
        float s10 = e10, s21 = e21;
#pragma unroll
        for (int o = 16; o; o >>= 1) {
            s10 += __shfl_xor_sync(~0u, s10, o);
            s21 += __shfl_xor_sync(~0u, s21, o);
        }
        w10v[c] = e10 / s10;
        w21v[c] = e21 / s21;
    }
    __syncthreads();

#pragma unroll
    for (int c = 0; c < 2; c++) {
        int j = w + c * 16;
        float inv_sg = 1.f / sgv[c];
        float4 t;
        t.x = S_CONST * inv_sg;
        t.y = -S_CONST * muv[c] * inv_sg;
        t.z = w21v[c] * INV_SQRT_2PI * inv_sg;
        t.w = w10v[c] * w0s[j] * INV_SQRT_2PI * inv_sg;
        s_tab[lane * K + j] = t;
    }
    __syncthreads();

    int chunk = blockIdx.x;
    int tsel = blockIdx.y;
    int g = chunk * 31 + lane;
    if (g > G - 1) g = G - 1;
    float x = XMIN + g * H_STEP;

#pragma unroll
    for (int c = 0; c < 2; c++) {
        int f = w + c * 16;
        float v = 0.f;
        if (tsel == 0) {
#pragma unroll
            for (int j = 0; j < K; j++) {
                float4 t = s_tab[f * K + j];
                float u = fmaf(x, t.x, t.y);
                v = fmaf(t.w, ex2f(-u * u), v);
            }
        } else {
#pragma unroll
            for (int i = 0; i < K; i++) {
                float4 t = s_tab[i * K + f];
                float u = fmaf(x, t.x, t.y);
                v = fmaf(t.z, ex2f(-u * u), v);
            }
        }
        float vn = __shfl_down_sync(0xffffffffu, v, 1);
        if (lane < 31 && g < G - 1) {
            // half index within row g: group (f>>2)*8, v slot (f&3), d slot (f&3)+4
            int hidx = g * (K * 2) + (f >> 2) * 8 + (f & 3);
            __half hv = __float2half(v);
            __half hd = __float2half(vn - v);
            if (tsel == 0) { g_tabF16[hidx] = hv; g_tabF16[hidx + 4] = hd; }
            else           { g_tabI16[hidx] = hv; g_tabI16[hidx + 4] = hd; }
        }
    }
}

// ---------------- main: fp16 tables, 4 samples per warp-iter ----------------
__global__ void __launch_bounds__(256, 4) tt_main(const float* __restrict__ X,
                                                  float* __restrict__ out,
                                                  int n, int ntasks) {
    __shared__ float4 sp[WPB][16];
    __shared__ float res[WPB][16];

    int tid = threadIdx.x;
    int lane = tid & 31;
    int w = tid >> 5;

    int task = blockIdx.x * WPB + w;
    if (task >= ntasks) return;

    int base = task * 16;

    if (lane < 16) {
        int sidx = base + lane;
        float2 x = make_float2(0.f, 0.f);
        if (sidx < n) x = ((const float2*)X)[sidx];
        float t0 = (x.x - XMIN) * INV_H;
        float t1 = (x.y - XMIN) * INV_H;
        float g0f = fminf(fmaxf(floorf(t0), 0.f), (float)(G - 2));
        float g1f = fminf(fmaxf(floorf(t1), 0.f), (float)(G - 2));
        sp[w][lane] = make_float4(g0f, t0 - g0f, g1f, t1 - g1f);
    }
    __syncwarp();

    const uint4* tF = (const uint4*)g_tabF16;  // row g = 8 uint4
    const uint4* tI = (const uint4*)g_tabI16;

    int group = lane >> 3;  // 0..3: which sample of the iter
    int sub = lane & 7;     // 0..7: comp group (comps 4*sub..4*sub+3)

    // preload params for this lane's 4 samples
    float4 pv[4];
#pragma unroll
    for (int i = 0; i < 4; i++) pv[i] = sp[w][i * 4 + group];

    float acc[4];
#pragma unroll
    for (int i = 0; i < 4; i++) {
        float4 p = pv[i];
        uint4 rF = __ldg(&tF[((int)p.x) * 8 + sub]);
        uint4 rI = __ldg(&tI[((int)p.z) * 8 + sub]);
        __half2 th0 = __float2half2_rn(p.y);
        __half2 th1 = __float2half2_rn(p.w);
        __half2 iF01 = __hfma2(th0, *(__half2*)&rF.z, *(__half2*)&rF.x);
        __half2 iF23 = __hfma2(th0, *(__half2*)&rF.w, *(__half2*)&rF.y);
        __half2 iI01 = __hfma2(th1, *(__half2*)&rI.z, *(__half2*)&rI.x);
        __half2 iI23 = __hfma2(th1, *(__half2*)&rI.w, *(__half2*)&rI.y);
        __half2 pr01 = __hmul2(iF01, iI01);
        __half2 pr23 = __hmul2(iF23, iI23);
        float2 a = __half22float2(pr01);
        float2 b = __half22float2(pr23);
        acc[i] = (a.x + a.y) + (b.x + b.y);
    }

    // reduce each acc over the 8-lane group
#pragma unroll
    for (int i = 0; i < 4; i++) {
        acc[i] += __shfl_xor_sync(~0u, acc[i], 1);
        acc[i] += __shfl_xor_sync(~0u, acc[i], 2);
        acc[i] += __shfl_xor_sync(~0u, acc[i], 4);
    }
    if (sub == 0) {
#pragma unroll
        for (int i = 0; i < 4; i++) res[w][i * 4 + group] = acc[i];
    }
    __syncwarp();

    if (lane < 16) {
        int sidx = base + lane;
        if (sidx < n) out[sidx] = __logf(res[w][lane] + EPS);
    }
}

extern "C" void kernel_launch(void* const* d_in, const int* in_sizes, int n_in,
                              void* d_out, int out_size) {
    const float* X     = (const float*)d_in[0];
    const float* Wk0   = (const float*)d_in[1];
    const float* Wk1k0 = (const float*)d_in[2];
    const float* Wk2k1 = (const float*)d_in[3];
    const float* mu    = (const float*)d_in[4];
    const float* sigma = (const float*)d_in[5];
    float* out = (float*)d_out;
    int n = in_sizes[0] / 2;

    build_kernel<<<dim3(NCHUNK, 2), 512>>>(Wk0, Wk1k0, Wk2k1, mu, sigma);
    int ntasks = (n + 15) / 16;
    int blocks = (ntasks + WPB - 1) / WPB;
    tt_main<<<blocks, 256>>>(X, out, n, ntasks);
}